// round 16
// baseline (speedup 1.0000x reference)
#include <cuda_runtime.h>
#include <cuda_fp16.h>
#include <math.h>
#include <stdint.h>

// ---------------- device globals (allowed scratch) ----------------
__device__ float g_wv[2][128];   // wv[c] = Wf[c] @ W1
__device__ float g_cc[2];        // cc[c] = bf[c] + Wf[c] @ b1
// B images: [seg][split] = 128dp x 128k fp16, row stride 256B, 64B-window swizzle
__device__ __half g_w0img[4][2][16384];

// B-image swizzle (64B window)
__host__ __device__ __forceinline__ uint32_t swzB(int row, int kByte) {
    return (uint32_t)row * 256u + (uint32_t)(kByte ^ (((row >> 1) & 3) << 4));
}

// ---------------- PTX helpers (sm_80+, legal on plain sm_100) ----------------
__device__ __forceinline__ uint32_t smem_u32(const void* p) {
    uint32_t a;
    asm("{ .reg .u64 t; cvta.to.shared.u64 t, %1; cvt.u32.u64 %0, t; }" : "=r"(a) : "l"(p));
    return a;
}
__device__ __forceinline__ void ldsm_x4(uint32_t* d, uint32_t addr) {
    asm volatile("ldmatrix.sync.aligned.m8n8.x4.shared.b16 {%0,%1,%2,%3}, [%4];"
                 : "=r"(d[0]), "=r"(d[1]), "=r"(d[2]), "=r"(d[3]) : "r"(addr));
}
__device__ __forceinline__ void mma_fp16(float* c, const uint32_t* a, uint32_t b0, uint32_t b1) {
    asm volatile(
        "mma.sync.aligned.m16n8k16.row.col.f32.f16.f16.f32 "
        "{%0,%1,%2,%3}, {%4,%5,%6,%7}, {%8,%9}, {%0,%1,%2,%3};"
        : "+f"(c[0]), "+f"(c[1]), "+f"(c[2]), "+f"(c[3])
        : "r"(a[0]), "r"(a[1]), "r"(a[2]), "r"(a[3]), "r"(b0), "r"(b1));
}
__device__ __forceinline__ void cp_async16(uint32_t dst, const void* src) {
    asm volatile("cp.async.cg.shared.global [%0], [%1], 16;" :: "r"(dst), "l"(src));
}
__device__ __forceinline__ void cp_commit() { asm volatile("cp.async.commit_group;" ::: "memory"); }
__device__ __forceinline__ void cp_wait0()  { asm volatile("cp.async.wait_group 0;" ::: "memory"); }
__device__ __forceinline__ void bar_sync(int id, int cnt) {
    asm volatile("bar.sync %0, %1;" :: "r"(id), "r"(cnt) : "memory");
}
__device__ __forceinline__ void bar_arrive(int id, int cnt) {
    asm volatile("bar.arrive %0, %1;" :: "r"(id), "r"(cnt) : "memory");
}

// ---------------- fused prep ----------------
__global__ void prep_all_kernel(const float* __restrict__ W0,
                                const float* __restrict__ W1,
                                const float* __restrict__ Wf,
                                const float* __restrict__ b1,
                                const float* __restrict__ bf) {
    if (blockIdx.x < 256) {
        int idx = blockIdx.x * 256 + threadIdx.x;   // 65536 = 4seg*128dp*128k
        int seg = idx >> 14;
        int dp  = (idx >> 7) & 127;
        int k   = idx & 127;
        float w = W0[dp * 512 + seg * 128 + k];
        __half v0 = __float2half_rn(w);
        float r1 = w - __half2float(v0);
        __half v1 = __float2half_rn(r1);
        uint32_t o = swzB(dp, k * 2) >> 1;
        g_w0img[seg][0][o] = v0;
        g_w0img[seg][1][o] = v1;
    } else {
        int t = threadIdx.x;
        int c = t >> 7, d = t & 127;
        double s = 0.0;
        for (int j = 0; j < 128; j++)
            s += (double)Wf[c * 128 + j] * (double)W1[j * 128 + d];
        g_wv[c][d] = (float)s;
        if (t < 2) {
            double cs = 0.0;
            for (int j = 0; j < 128; j++)
                cs += (double)Wf[t * 128 + j] * (double)b1[j];
            g_cc[t] = (float)(cs + (double)bf[t]);
        }
    }
}

// ---------------- main kernel: warp-specialized producer/consumer ----------------
// 512 threads, 1 CTA/SM. Warps 0-7: MMA consumers (128e x 128dp, warp tile 32e x 64dp,
// identical fragment mapping to the verified R13 kernel). Warps 8-15: A builders.
// A: FULL double buffer, 2 x (2 splits x 128e x 128k fp16, 256B rows, 128B-window swz).
// Builders build seg s+1 while consumers run seg s. Named barriers:
//   id 1/2 : A buf0/buf1 ready  (256 builder arrives + 256 MMA syncs = 512)
//   id 3/4 : A buf0/buf1 free   (256 MMA arrives + 256 builder syncs = 512)
//   id 5   : MMA-warps-only B-chunk barrier (count 256)
// B: cp.async double-buffered 16KB chunks, owned by MMA warps (prefetch distance 1).
#define SM_A     0
#define SM_B     131072
#define SM_CONST 163840
#define SM_RED   165376
#define SM_TOTAL 167424

__global__ void __launch_bounds__(512, 1)
advers_mask_edge_ws(const float* __restrict__ h,
                    const float* __restrict__ b0,
                    const float* __restrict__ u,
                    const int* __restrict__ src,
                    const int* __restrict__ dst,
                    float* __restrict__ out,
                    int E, int N) {
    extern __shared__ char smem[];
    const uint32_t sbase = smem_u32(smem);
    float* sc   = (float*)(smem + SM_CONST);
    float* sred = (float*)(smem + SM_RED);

    const int tid = threadIdx.x;
    const int wid = tid >> 5;
    const int lid = tid & 31;
    const int eb  = blockIdx.x * 128;

    if (tid < 128) {
        sc[tid]       = b0[tid];
        sc[128 + tid] = g_wv[0][tid];
        sc[256 + tid] = g_wv[1][tid];
    }

    if (wid >= 8) {
        // ================= BUILDER warps (8-15) =================
        const int bw = wid - 8;          // owns edges bw*16 .. bw*16+15
        int myidx;
        {
            int e = eb + bw * 16 + (lid & 15);
            if (e >= E) e = E - 1;
            myidx = (lid < 16) ? src[e] : dst[e];
        }
        const int e_base = bw * 16;

        for (int s = 0; s < 4; s++) {
            if (s >= 2) bar_sync(3 + (s & 1), 512);    // wait buffer free
            const float* hsB = h + (size_t)(s >> 1) * N * 128;
            const float* hdB = h + (size_t)(s & 1) * N * 128;
            char* abuf = smem + SM_A + (s & 1) * 65536;

#pragma unroll
            for (int g4 = 0; g4 < 4; g4++) {
                float4 sv[4], dv[4];
#pragma unroll
                for (int j = 0; j < 4; j++) {
                    int ee = g4 * 4 + j;
                    int se = __shfl_sync(0xffffffffu, myidx, ee);
                    int de = __shfl_sync(0xffffffffu, myidx, 16 + ee);
                    sv[j] = *(const float4*)(hsB + (size_t)se * 128 + lid * 4);
                    dv[j] = *(const float4*)(hdB + (size_t)de * 128 + lid * 4);
                }
#pragma unroll
                for (int j = 0; j < 4; j++) {
                    int row = e_base + g4 * 4 + j;
                    float p0 = sv[j].x * dv[j].x;
                    float p1 = sv[j].y * dv[j].y;
                    float p2 = sv[j].z * dv[j].z;
                    float p3 = sv[j].w * dv[j].w;
                    __half a0 = __float2half_rn(p0), a1h = __float2half_rn(p1);
                    __half a2 = __float2half_rn(p2), a3 = __float2half_rn(p3);
                    float q0 = p0 - __half2float(a0), q1 = p1 - __half2float(a1h);
                    float q2 = p2 - __half2float(a2), q3 = p3 - __half2float(a3);
                    uint32_t u0a = (uint32_t)__half_as_ushort(a0) |
                                   ((uint32_t)__half_as_ushort(a1h) << 16);
                    uint32_t u0b = (uint32_t)__half_as_ushort(a2) |
                                   ((uint32_t)__half_as_ushort(a3) << 16);
                    __half b0h = __float2half_rn(q0), b1h = __float2half_rn(q1);
                    __half b2h = __float2half_rn(q2), b3h = __float2half_rn(q3);
                    uint32_t u1a = (uint32_t)__half_as_ushort(b0h) |
                                   ((uint32_t)__half_as_ushort(b1h) << 16);
                    uint32_t u1b = (uint32_t)__half_as_ushort(b2h) |
                                   ((uint32_t)__half_as_ushort(b3h) << 16);
                    uint32_t kB  = (uint32_t)(lid * 8);   // fp16 cols 4l..4l+3
                    uint32_t off = (uint32_t)row * 256u + (kB ^ (((uint32_t)row & 7u) << 4));
                    *(uint2*)(abuf + off)         = make_uint2(u0a, u0b);
                    *(uint2*)(abuf + 32768 + off) = make_uint2(u1a, u1b);
                }
            }
            asm volatile("membar.cta;" ::: "memory");
            bar_arrive(1 + (s & 1), 512);              // signal buffer ready
        }
    } else {
        // ================= MMA warps (0-7) =================
        const int we = wid >> 1;     // 0..3 edge group
        const int wd = wid & 1;      // 0..1 dp half

        const int g = lid >> 3, r = lid & 7;
        uint32_t aRowTerm[2];
#pragma unroll
        for (int mt = 0; mt < 2; mt++)
            aRowTerm[mt] = (uint32_t)(we * 32 + mt * 16 + (g & 1) * 8 + r) * 256u;
        uint32_t bRowTerm[4];
#pragma unroll
        for (int nt2 = 0; nt2 < 4; nt2++)
            bRowTerm[nt2] = (uint32_t)(wd * 64 + nt2 * 16 + (g >> 1) * 8 + r) * 64u;
        const uint32_t aKsel = (uint32_t)((g >> 1) * 16);
        const uint32_t bKsel = (uint32_t)((g & 1) * 16);
        const uint32_t rx    = (uint32_t)(r << 4);
        const uint32_t rbx   = (uint32_t)(((r >> 1) & 3) << 4);

        float acc[2][8][4];
#pragma unroll
        for (int mt = 0; mt < 2; mt++)
#pragma unroll
            for (int nt = 0; nt < 8; nt++)
#pragma unroll
                for (int i = 0; i < 4; i++) acc[mt][nt][i] = 0.f;

        // prologue: prefetch B chunk 0 into buf 0 (256 MMA threads cover 16KB)
        {
            const char* bsrc = (const char*)&g_w0img[0][0][0];
            uint32_t dst0 = sbase + SM_B;
#pragma unroll
            for (int i = 0; i < 4; i++) {
                int idx = tid + i * 256;
                int s2 = idx >> 9, j = idx & 511, row = j >> 2, gg = j & 3;
                cp_async16(dst0 + s2 * 8192 + row * 64 + gg * 16,
                           bsrc + s2 * 32768 + row * 256 + gg * 16);
            }
            cp_commit();
        }

        for (int cg = 0; cg < 16; cg++) {
            const int buf = cg & 1;
            const int c   = cg & 3;
            const int s   = cg >> 2;
            if (c == 0) bar_sync(1 + (s & 1), 512);   // wait A(seg s) ready
            cp_wait0();
            bar_sync(5, 256);                          // B(cg) visible to all MMA warps

            if (cg + 1 < 16) {
                const int seg_n = (cg + 1) >> 2, sub_n = (cg + 1) & 3;
                const char* bsrc = (const char*)&g_w0img[seg_n][0][0];
                uint32_t dst0 = sbase + SM_B + (uint32_t)(buf ^ 1) * 16384u;
#pragma unroll
                for (int i = 0; i < 4; i++) {
                    int idx = tid + i * 256;
                    int s2 = idx >> 9, j = idx & 511, row = j >> 2, gg = j & 3;
                    cp_async16(dst0 + s2 * 8192 + row * 64 + gg * 16,
                               bsrc + s2 * 32768 + row * 256 + sub_n * 64 + gg * 16);
                }
                cp_commit();
            }

            const uint32_t abuf  = sbase + SM_A + (uint32_t)(s & 1) * 65536u;
            const uint32_t bbase = sbase + SM_B + (uint32_t)buf * 16384u;
#pragma unroll
            for (int kst = 0; kst < 2; kst++) {
                const uint32_t akb = (uint32_t)(c * 64 + kst * 32 + aKsel) ^ rx;
                const uint32_t bkb = (uint32_t)(kst * 32 + bKsel) ^ rbx;

                uint32_t afr[2][2][4];
#pragma unroll
                for (int sp = 0; sp < 2; sp++)
#pragma unroll
                    for (int mt = 0; mt < 2; mt++)
                        ldsm_x4(afr[sp][mt], abuf + sp * 32768 + aRowTerm[mt] + akb);

#pragma unroll
                for (int nt2 = 0; nt2 < 4; nt2++) {
                    uint32_t bf0[4], bf1[4];
                    ldsm_x4(bf0, bbase + bRowTerm[nt2] + bkb);          // split 0
                    ldsm_x4(bf1, bbase + 8192 + bRowTerm[nt2] + bkb);   // split 1
#pragma unroll
                    for (int mt = 0; mt < 2; mt++) {
                        float* c0 = acc[mt][nt2 * 2 + 0];
                        float* c1 = acc[mt][nt2 * 2 + 1];
                        mma_fp16(c0, afr[0][mt], bf0[0], bf0[1]);   // a0*b0
                        mma_fp16(c1, afr[0][mt], bf0[2], bf0[3]);
                        mma_fp16(c0, afr[0][mt], bf1[0], bf1[1]);   // a0*b1
                        mma_fp16(c1, afr[0][mt], bf1[2], bf1[3]);
                        mma_fp16(c0, afr[1][mt], bf0[0], bf0[1]);   // a1*b0
                        mma_fp16(c1, afr[1][mt], bf0[2], bf0[3]);
                    }
                }
            }

            if (c == 3 && s < 2) bar_arrive(3 + s, 512);   // free A buf s for seg s+2
        }

        // ---- epilogue: relu + dual dot from C fragments ----
        const int tig = lid & 3;
#pragma unroll
        for (int mt = 0; mt < 2; mt++) {
#pragma unroll
            for (int hr = 0; hr < 2; hr++) {
                float s0 = 0.f, s1 = 0.f;
#pragma unroll
                for (int nt = 0; nt < 8; nt++) {
                    int dp0 = wd * 64 + (nt >> 1) * 16 + (nt & 1) * 8 + tig * 2;
                    float x0 = fmaxf(acc[mt][nt][hr * 2 + 0] + sc[dp0], 0.f);
                    float x1 = fmaxf(acc[mt][nt][hr * 2 + 1] + sc[dp0 + 1], 0.f);
                    s0 = fmaf(x0, sc[128 + dp0], fmaf(x1, sc[128 + dp0 + 1], s0));
                    s1 = fmaf(x0, sc[256 + dp0], fmaf(x1, sc[256 + dp0 + 1], s1));
                }
                s0 += __shfl_xor_sync(0xffffffffu, s0, 1);
                s0 += __shfl_xor_sync(0xffffffffu, s0, 2);
                s1 += __shfl_xor_sync(0xffffffffu, s1, 1);
                s1 += __shfl_xor_sync(0xffffffffu, s1, 2);
                if (tig == 0) {
                    int e_row = we * 32 + mt * 16 + hr * 8 + (lid >> 2);
                    sred[(wd * 128 + e_row) * 2 + 0] = s0;
                    sred[(wd * 128 + e_row) * 2 + 1] = s1;
                }
            }
        }
    }

    __syncthreads();   // all 512: sred visible

    if (tid < 128) {
        int e = eb + tid;
        if (e < E) {
            float s0 = sred[tid * 2 + 0] + sred[(128 + tid) * 2 + 0];
            float s1 = sred[tid * 2 + 1] + sred[(128 + tid) * 2 + 1];
            float u0 = u[2 * e], u1 = u[2 * e + 1];
            float gg0 = -logf(-logf(u0 + 1e-10f) + 1e-10f);
            float gg1 = -logf(-logf(u1 + 1e-10f) + 1e-10f);
            float v0 = s0 + g_cc[0] + gg0;
            float v1 = s1 + g_cc[1] + gg1;
            bool one = (v1 > v0);   // argmax ties -> class 0
            out[2 * e]     = one ? 0.f : 1.f;
            out[2 * e + 1] = one ? 1.f : 0.f;
        }
    }
}

extern "C" void kernel_launch(void* const* d_in, const int* in_sizes, int n_in,
                              void* d_out, int out_size) {
    const float* h  = (const float*)d_in[0];
    const float* W0 = (const float*)d_in[1];
    const float* b0 = (const float*)d_in[2];
    const float* W1 = (const float*)d_in[3];
    const float* b1 = (const float*)d_in[4];
    const float* Wf = (const float*)d_in[5];
    const float* bf = (const float*)d_in[6];
    const float* u  = (const float*)d_in[7];
    const int*   src = (const int*)d_in[8];
    const int*   dst = (const int*)d_in[9];
    float* out = (float*)d_out;

    const int E = in_sizes[8];
    const int N = in_sizes[0] / 256;   // h is (L=2, N, D=128)

    prep_all_kernel<<<257, 256>>>(W0, W1, Wf, b1, bf);

    cudaFuncSetAttribute(advers_mask_edge_ws,
                         cudaFuncAttributeMaxDynamicSharedMemorySize, SM_TOTAL);
    int blocks = (E + 127) / 128;
    advers_mask_edge_ws<<<blocks, 512, SM_TOTAL>>>(h, b0, u, src, dst, out, E, N);
}

// round 17
// speedup vs baseline: 1.0694x; 1.0694x over previous
#include <cuda_runtime.h>
#include <cuda_fp16.h>
#include <math.h>
#include <stdint.h>

// ---------------- device globals (allowed scratch) ----------------
__device__ float g_wv[2][128];   // wv[c] = Wf[c] @ W1
__device__ float g_cc[2];        // cc[c] = bf[c] + Wf[c] @ b1
// B images: [seg][split] = 128dp x 128k fp16, row stride 256B, 64B-window swizzle
__device__ __half g_w0img[4][2][16384];

// B-image swizzle (64B window): off = row*256 + (kByte ^ (((row>>1)&3)<<4))
__host__ __device__ __forceinline__ uint32_t swzB(int row, int kByte) {
    return (uint32_t)row * 256u + (uint32_t)(kByte ^ (((row >> 1) & 3) << 4));
}

// ---------------- PTX helpers (sm_80+, legal on plain sm_100) ----------------
__device__ __forceinline__ uint32_t smem_u32(const void* p) {
    uint32_t a;
    asm("{ .reg .u64 t; cvta.to.shared.u64 t, %1; cvt.u32.u64 %0, t; }" : "=r"(a) : "l"(p));
    return a;
}
__device__ __forceinline__ void ldsm_x4(uint32_t* d, uint32_t addr) {
    asm volatile("ldmatrix.sync.aligned.m8n8.x4.shared.b16 {%0,%1,%2,%3}, [%4];"
                 : "=r"(d[0]), "=r"(d[1]), "=r"(d[2]), "=r"(d[3]) : "r"(addr));
}
__device__ __forceinline__ void mma_fp16(float* c, const uint32_t* a, uint32_t b0, uint32_t b1) {
    asm volatile(
        "mma.sync.aligned.m16n8k16.row.col.f32.f16.f16.f32 "
        "{%0,%1,%2,%3}, {%4,%5,%6,%7}, {%8,%9}, {%0,%1,%2,%3};"
        : "+f"(c[0]), "+f"(c[1]), "+f"(c[2]), "+f"(c[3])
        : "r"(a[0]), "r"(a[1]), "r"(a[2]), "r"(a[3]), "r"(b0), "r"(b1));
}
__device__ __forceinline__ void cp_async16(uint32_t dst, const void* src) {
    asm volatile("cp.async.cg.shared.global [%0], [%1], 16;" :: "r"(dst), "l"(src));
}
__device__ __forceinline__ void cp_commit() { asm volatile("cp.async.commit_group;" ::: "memory"); }
__device__ __forceinline__ void cp_wait0()  { asm volatile("cp.async.wait_group 0;" ::: "memory"); }

// ---------------- fused prep ----------------
__global__ void prep_all_kernel(const float* __restrict__ W0,
                                const float* __restrict__ W1,
                                const float* __restrict__ Wf,
                                const float* __restrict__ b1,
                                const float* __restrict__ bf) {
    if (blockIdx.x < 256) {
        int idx = blockIdx.x * 256 + threadIdx.x;   // 65536 = 4seg*128dp*128k
        int seg = idx >> 14;
        int dp  = (idx >> 7) & 127;
        int k   = idx & 127;
        float w = W0[dp * 512 + seg * 128 + k];
        __half v0 = __float2half_rn(w);
        float r1 = w - __half2float(v0);
        __half v1 = __float2half_rn(r1);
        uint32_t o = swzB(dp, k * 2) >> 1;
        g_w0img[seg][0][o] = v0;
        g_w0img[seg][1][o] = v1;
    } else {
        int t = threadIdx.x;
        int c = t >> 7, d = t & 127;
        double s = 0.0;
        for (int j = 0; j < 128; j++)
            s += (double)Wf[c * 128 + j] * (double)W1[j * 128 + d];
        g_wv[c][d] = (float)s;
        if (t < 2) {
            double cs = 0.0;
            for (int j = 0; j < 128; j++)
                cs += (double)Wf[t * 128 + j] * (double)b1[j];
            g_cc[t] = (float)(cs + (double)bf[t]);
        }
    }
}

// ---------------- main kernel (R13 structure + wave-parity seg desync) ----------------
// Block: 128 edges x 128 dp, 256 threads = 8 warps. Warp tile: 32e x 64dp.
// K loop: 16 chunks of 32k. Seg ORDER rotated by 2 for odd waves so co-resident
// CTAs' A-build phases anti-correlate (build hides under the other CTA's MMA).
// A rebuilt per seg (warp-cooperative coalesced gathers). B double-buffered
// 16KB chunks via cp.async, prefetch distance 1.
// smem:
//   [0,     65536)  A: 2 splits x (128e x 128k fp16, 128B-window swz, stride 256B)
//   [65536, 98304)  B: 2 bufs x (2 splits x 128dp x 32k fp16, 64B rows)
//   [98304, 99840)  consts: b0[128], wv0[128], wv1[128]
//   [99840,101888)  s_red[2][128][2]
#define SM_A     0
#define SM_B     65536
#define SM_CONST 98304
#define SM_RED   99840
#define SM_TOTAL 101888

__global__ void __launch_bounds__(256, 2)
advers_mask_edge_mma(const float* __restrict__ h,
                     const float* __restrict__ b0,
                     const float* __restrict__ u,
                     const int* __restrict__ src,
                     const int* __restrict__ dst,
                     float* __restrict__ out,
                     int E, int N) {
    extern __shared__ char smem[];
    const uint32_t sbase = smem_u32(smem);
    float* sc   = (float*)(smem + SM_CONST);
    float* sred = (float*)(smem + SM_RED);

    const int tid = threadIdx.x;
    const int wid = tid >> 5;
    const int lid = tid & 31;
    const int we  = wid >> 1;     // 0..3 edge group
    const int wd  = wid & 1;      // 0..1 dp half
    const int eb  = blockIdx.x * 128;
    // wave-parity desync: odd waves process segs in order 2,3,0,1
    const int soff = ((blockIdx.x / 148) & 1) * 2;

    if (tid < 128) {
        sc[tid]       = b0[tid];
        sc[128 + tid] = g_wv[0][tid];
        sc[256 + tid] = g_wv[1][tid];
    }

    // warp owns 16 edges; lanes 0-15 hold src idx, lanes 16-31 hold dst idx
    int myidx;
    {
        int e = eb + wid * 16 + (lid & 15);
        if (e >= E) e = E - 1;
        myidx = (lid < 16) ? src[e] : dst[e];
    }

    // ldmatrix per-lane addressing (fragment mapping verified R11-R13)
    const int g = lid >> 3, r = lid & 7;
    uint32_t aRowTerm[2];
#pragma unroll
    for (int mt = 0; mt < 2; mt++)
        aRowTerm[mt] = (uint32_t)(we * 32 + mt * 16 + (g & 1) * 8 + r) * 256u;
    uint32_t bRowTerm[4];
#pragma unroll
    for (int nt2 = 0; nt2 < 4; nt2++)
        bRowTerm[nt2] = (uint32_t)(wd * 64 + nt2 * 16 + (g >> 1) * 8 + r) * 64u;
    const uint32_t aKsel = (uint32_t)((g >> 1) * 16);
    const uint32_t bKsel = (uint32_t)((g & 1) * 16);
    const uint32_t rx    = (uint32_t)(r << 4);
    const uint32_t rbx   = (uint32_t)(((r >> 1) & 3) << 4);

    float acc[2][8][4];
#pragma unroll
    for (int mt = 0; mt < 2; mt++)
#pragma unroll
        for (int nt = 0; nt < 8; nt++)
#pragma unroll
            for (int i = 0; i < 4; i++) acc[mt][nt][i] = 0.f;

    // ---- prologue: prefetch B chunk 0 (mapped seg) into buf 0 ----
    {
        const char* bsrc = (const char*)&g_w0img[soff][0][0];
        uint32_t dst0 = sbase + SM_B;
#pragma unroll
        for (int i = 0; i < 4; i++) {
            int idx = tid + i * 256;
            int s = idx >> 9, j = idx & 511, row = j >> 2, gg = j & 3;
            cp_async16(dst0 + s * 8192 + row * 64 + gg * 16,
                       bsrc + s * 32768 + row * 256 + gg * 16);
        }
        cp_commit();
    }

    for (int cg = 0; cg < 16; cg++) {
        const int buf = cg & 1;
        cp_wait0();          // B(cg) copies arrived
        __syncthreads();     // all B(cg) visible; all warps retired MMA(cg-1)

        // prefetch B(cg+1) (mapped seg) into freed buffer
        if (cg + 1 < 16) {
            const int seg_n = (((cg + 1) >> 2) + soff) & 3, sub_n = (cg + 1) & 3;
            const char* bsrc = (const char*)&g_w0img[seg_n][0][0];
            uint32_t dst0 = sbase + SM_B + (uint32_t)(buf ^ 1) * 16384u;
#pragma unroll
            for (int i = 0; i < 4; i++) {
                int idx = tid + i * 256;
                int s = idx >> 9, j = idx & 511, row = j >> 2, gg = j & 3;
                cp_async16(dst0 + s * 8192 + row * 64 + gg * 16,
                           bsrc + s * 32768 + row * 256 + sub_n * 64 + gg * 16);
            }
            cp_commit();
        }

        // ---- rebuild A at seg starts: warp-cooperative coalesced gathers ----
        if ((cg & 3) == 0) {
            const int seg = ((cg >> 2) + soff) & 3;
            const int l0 = seg >> 1, l1 = seg & 1;
            const float* hsB = h + (size_t)l0 * N * 128;
            const float* hdB = h + (size_t)l1 * N * 128;
            const int e_base = wid * 16;

#pragma unroll
            for (int g4 = 0; g4 < 4; g4++) {
                float4 sv[4], dv[4];
#pragma unroll
                for (int j = 0; j < 4; j++) {
                    int ee = g4 * 4 + j;
                    int se = __shfl_sync(0xffffffffu, myidx, ee);
                    int de = __shfl_sync(0xffffffffu, myidx, 16 + ee);
                    sv[j] = *(const float4*)(hsB + (size_t)se * 128 + lid * 4);
                    dv[j] = *(const float4*)(hdB + (size_t)de * 128 + lid * 4);
                }
#pragma unroll
                for (int j = 0; j < 4; j++) {
                    int row = e_base + g4 * 4 + j;
                    float p0 = sv[j].x * dv[j].x;
                    float p1 = sv[j].y * dv[j].y;
                    float p2 = sv[j].z * dv[j].z;
                    float p3 = sv[j].w * dv[j].w;
                    __half a0 = __float2half_rn(p0), a1h = __float2half_rn(p1);
                    __half a2 = __float2half_rn(p2), a3 = __float2half_rn(p3);
                    float q0 = p0 - __half2float(a0), q1 = p1 - __half2float(a1h);
                    float q2 = p2 - __half2float(a2), q3 = p3 - __half2float(a3);
                    uint32_t u0a = (uint32_t)__half_as_ushort(a0) |
                                   ((uint32_t)__half_as_ushort(a1h) << 16);
                    uint32_t u0b = (uint32_t)__half_as_ushort(a2) |
                                   ((uint32_t)__half_as_ushort(a3) << 16);
                    __half b0h = __float2half_rn(q0), b1h = __float2half_rn(q1);
                    __half b2h = __float2half_rn(q2), b3h = __float2half_rn(q3);
                    uint32_t u1a = (uint32_t)__half_as_ushort(b0h) |
                                   ((uint32_t)__half_as_ushort(b1h) << 16);
                    uint32_t u1b = (uint32_t)__half_as_ushort(b2h) |
                                   ((uint32_t)__half_as_ushort(b3h) << 16);
                    uint32_t soff2 = (uint32_t)row * 256u +
                                     (((uint32_t)(lid * 8)) ^ (((uint32_t)row & 7u) << 4));
                    *(uint2*)(smem + SM_A + soff2)         = make_uint2(u0a, u0b);
                    *(uint2*)(smem + SM_A + 32768 + soff2) = make_uint2(u1a, u1b);
                }
            }
            __syncthreads();   // A visible before MMA
        }

        // ---- MMA chunk: 2 K-steps of 16; 3 split-combos (a0b0, a0b1, a1b0) ----
        const uint32_t bbase = sbase + SM_B + (uint32_t)buf * 16384u;
#pragma unroll
        for (int kst = 0; kst < 2; kst++) {
            const uint32_t akb = (uint32_t)((cg & 3) * 64 + kst * 32 + aKsel) ^ rx;
            const uint32_t bkb = (uint32_t)(kst * 32 + bKsel) ^ rbx;

            uint32_t afr[2][2][4];
#pragma unroll
            for (int s = 0; s < 2; s++)
#pragma unroll
                for (int mt = 0; mt < 2; mt++)
                    ldsm_x4(afr[s][mt], sbase + SM_A + s * 32768 + aRowTerm[mt] + akb);

#pragma unroll
            for (int nt2 = 0; nt2 < 4; nt2++) {
                uint32_t bf0[4], bf1[4];
                ldsm_x4(bf0, bbase + bRowTerm[nt2] + bkb);          // split 0
                ldsm_x4(bf1, bbase + 8192 + bRowTerm[nt2] + bkb);   // split 1
#pragma unroll
                for (int mt = 0; mt < 2; mt++) {
                    float* c0 = acc[mt][nt2 * 2 + 0];
                    float* c1 = acc[mt][nt2 * 2 + 1];
                    mma_fp16(c0, afr[0][mt], bf0[0], bf0[1]);   // a0*b0
                    mma_fp16(c1, afr[0][mt], bf0[2], bf0[3]);
                    mma_fp16(c0, afr[0][mt], bf1[0], bf1[1]);   // a0*b1
                    mma_fp16(c1, afr[0][mt], bf1[2], bf1[3]);
                    mma_fp16(c0, afr[1][mt], bf0[0], bf0[1]);   // a1*b0
                    mma_fp16(c1, afr[1][mt], bf0[2], bf0[3]);
                }
            }
        }
    }
    __syncthreads();

    // ---- epilogue: relu + dual dot from C fragments ----
    const int tig = lid & 3;
#pragma unroll
    for (int mt = 0; mt < 2; mt++) {
#pragma unroll
        for (int hr = 0; hr < 2; hr++) {
            float s0 = 0.f, s1 = 0.f;
#pragma unroll
            for (int nt = 0; nt < 8; nt++) {
                int dp0 = wd * 64 + (nt >> 1) * 16 + (nt & 1) * 8 + tig * 2;
                float x0 = fmaxf(acc[mt][nt][hr * 2 + 0] + sc[dp0], 0.f);
                float x1 = fmaxf(acc[mt][nt][hr * 2 + 1] + sc[dp0 + 1], 0.f);
                s0 = fmaf(x0, sc[128 + dp0], fmaf(x1, sc[128 + dp0 + 1], s0));
                s1 = fmaf(x0, sc[256 + dp0], fmaf(x1, sc[256 + dp0 + 1], s1));
            }
            s0 += __shfl_xor_sync(0xffffffffu, s0, 1);
            s0 += __shfl_xor_sync(0xffffffffu, s0, 2);
            s1 += __shfl_xor_sync(0xffffffffu, s1, 1);
            s1 += __shfl_xor_sync(0xffffffffu, s1, 2);
            if (tig == 0) {
                int e_row = we * 32 + mt * 16 + hr * 8 + (lid >> 2);
                sred[(wd * 128 + e_row) * 2 + 0] = s0;
                sred[(wd * 128 + e_row) * 2 + 1] = s1;
            }
        }
    }
    __syncthreads();

    if (tid < 128) {
        int e = eb + tid;
        if (e < E) {
            float s0 = sred[tid * 2 + 0] + sred[(128 + tid) * 2 + 0];
            float s1 = sred[tid * 2 + 1] + sred[(128 + tid) * 2 + 1];
            float u0 = u[2 * e], u1 = u[2 * e + 1];
            float gg0 = -logf(-logf(u0 + 1e-10f) + 1e-10f);
            float gg1 = -logf(-logf(u1 + 1e-10f) + 1e-10f);
            float v0 = s0 + g_cc[0] + gg0;
            float v1 = s1 + g_cc[1] + gg1;
            bool one = (v1 > v0);   // argmax ties -> class 0
            out[2 * e]     = one ? 0.f : 1.f;
            out[2 * e + 1] = one ? 1.f : 0.f;
        }
    }
}

extern "C" void kernel_launch(void* const* d_in, const int* in_sizes, int n_in,
                              void* d_out, int out_size) {
    const float* h  = (const float*)d_in[0];
    const float* W0 = (const float*)d_in[1];
    const float* b0 = (const float*)d_in[2];
    const float* W1 = (const float*)d_in[3];
    const float* b1 = (const float*)d_in[4];
    const float* Wf = (const float*)d_in[5];
    const float* bf = (const float*)d_in[6];
    const float* u  = (const float*)d_in[7];
    const int*   src = (const int*)d_in[8];
    const int*   dst = (const int*)d_in[9];
    float* out = (float*)d_out;

    const int E = in_sizes[8];
    const int N = in_sizes[0] / 256;   // h is (L=2, N, D=128)

    prep_all_kernel<<<257, 256>>>(W0, W1, Wf, b1, bf);

    cudaFuncSetAttribute(advers_mask_edge_mma,
                         cudaFuncAttributeMaxDynamicSharedMemorySize, SM_TOTAL);
    int blocks = (E + 127) / 128;
    advers_mask_edge_mma<<<blocks, 256, SM_TOTAL>>>(h, b0, u, src, dst, out, E, N);
}